// round 16
// baseline (speedup 1.0000x reference)
#include <cuda_runtime.h>
#include <cuda_fp16.h>
#include <math.h>
#include <stdint.h>

#define SSP 16129   // 127*127
#define XDP 16136   // padded fp16 xd row stride (16B-aligned rows)
#define HW  127
#define BB  4
#define CC  256
#define IMG 256
#define IMGSZ 65536
#define ASP 132

// ---------------- scratch (device globals; no allocation) ----------------
__device__ float g_xd[(size_t)BB*CC*SSP];                   // downsampled x fp32 [b][c][s]
__device__ __align__(16) __half g_xdh[(size_t)BB*CC*XDP];   // downsampled x fp16 [b][c][s(pad)]
__device__ float g_qk[(size_t)BB*SSP*64];                   // q(0..31)|k(32..63) fp32 [b][s][64]
__device__ float g_a [(size_t)BB*SSP*64];                   // resized attn fp32 [b][s][64]
__device__ __align__(16) __half g_wqkh[64*256];             // wq|wk fp16
__device__ __align__(16) __half g_wvh[256*256];             // wv fp16
__device__ __align__(16) __half g_Eh[(size_t)BB*SSP*256];   // energies fp16 (rows of 256: H|W)
__device__ __align__(16) __half g_Ah[(size_t)BB*SSP*256];   // a-energies fp16
__device__ __align__(16) __half g_Sh[(size_t)BB*SSP*256];   // softmax S fp16
__device__ __align__(16) __half g_vh[(size_t)BB*SSP*256];   // v fp16 [b][s][256]
__device__ __align__(16) __half g_oH[(size_t)BB*CC*HW*128]; // outH [b][c][j][i(pad128)]
__device__ __align__(16) __half g_oW[(size_t)BB*CC*HW*128]; // outW [b][c][i][j(pad128)]

// ---------------- f32x2 helpers ----------------
__device__ __forceinline__ unsigned long long dup2(float x) {
    unsigned long long r;
    asm("mov.b64 %0, {%1, %1};" : "=l"(r) : "f"(x));
    return r;
}
__device__ __forceinline__ void fma2(unsigned long long& d, unsigned long long a, unsigned long long b) {
    asm("fma.rn.f32x2 %0, %1, %2, %0;" : "+l"(d) : "l"(a), "l"(b));
}
__device__ __forceinline__ float2 unpack2(unsigned long long v) {
    float2 r;
    asm("mov.b64 {%0, %1}, %2;" : "=f"(r.x), "=f"(r.y) : "l"(v));
    return r;
}

// R2 broadcast microkernels. As/Bs: [16][stride] floats (m/n contiguous).
__device__ __forceinline__ void micro128(const float* As, const float* Bs,
                                         unsigned long long acc[8][4], int tx, int ty) {
    #pragma unroll
    for (int kk = 0; kk < 16; kk++) {
        float4 x0 = *(const float4*)&As[kk*ASP + tx*4];
        float4 x1 = *(const float4*)&As[kk*ASP + 64 + tx*4];
        ulonglong2 w0 = *(const ulonglong2*)&Bs[kk*ASP + ty*8];
        ulonglong2 w1 = *(const ulonglong2*)&Bs[kk*ASP + ty*8 + 4];
        unsigned long long xs[8];
        xs[0]=dup2(x0.x); xs[1]=dup2(x0.y); xs[2]=dup2(x0.z); xs[3]=dup2(x0.w);
        xs[4]=dup2(x1.x); xs[5]=dup2(x1.y); xs[6]=dup2(x1.z); xs[7]=dup2(x1.w);
        #pragma unroll
        for (int m = 0; m < 8; m++) {
            fma2(acc[m][0], xs[m], w0.x);
            fma2(acc[m][1], xs[m], w0.y);
            fma2(acc[m][2], xs[m], w1.x);
            fma2(acc[m][3], xs[m], w1.y);
        }
    }
}
__device__ __forceinline__ void micro64(const float* As, const float* Bs,
                                        unsigned long long acc[8][2], int tx, int ty) {
    #pragma unroll
    for (int kk = 0; kk < 16; kk++) {
        float4 x0 = *(const float4*)&As[kk*ASP + tx*4];
        float4 x1 = *(const float4*)&As[kk*ASP + 64 + tx*4];
        ulonglong2 w0 = *(const ulonglong2*)&Bs[kk*68 + ty*4];
        unsigned long long xs[8];
        xs[0]=dup2(x0.x); xs[1]=dup2(x0.y); xs[2]=dup2(x0.z); xs[3]=dup2(x0.w);
        xs[4]=dup2(x1.x); xs[5]=dup2(x1.y); xs[6]=dup2(x1.z); xs[7]=dup2(x1.w);
        #pragma unroll
        for (int m = 0; m < 8; m++) {
            fma2(acc[m][0], xs[m], w0.x);
            fma2(acc[m][1], xs[m], w0.y);
        }
    }
}

// ---------------- 0) weight prep: wq|wk and wv fp32 -> fp16 ----------------
__global__ void prep_w_kernel(const float* __restrict__ wq, const float* __restrict__ wk,
                              const float* __restrict__ wv) {
    int idx = blockIdx.x * 256 + threadIdx.x;   // 320 blocks
    if (idx < 64*256) {
        int n = idx >> 8, k = idx & 255;
        float v = (n < 32) ? wq[n*256 + k] : wk[(n-32)*256 + k];
        g_wqkh[idx] = __float2half(v);
    } else {
        int e = idx - 64*256;                   // 0 .. 65535
        g_wvh[e] = __float2half(wv[e]);
    }
}

// ---------------- 1) depthwise 4x4 stride-2 conv — smem-tiled (R14) ----------------
__global__ __launch_bounds__(256) void conv_down_kernel(const float* __restrict__ x,
                                                        const float* __restrict__ wd) {
    __shared__ __align__(16) float xs[18*256];
    int bc = blockIdx.x;            // b*256 + c
    int i0 = blockIdx.y * 8;
    int c  = bc & 255;
    int tid = threadIdx.x;
    float wr[16];
    #pragma unroll
    for (int t = 0; t < 16; t++) wr[t] = wd[c*16 + t];
    const float* xb = x + (size_t)bc * IMGSZ;
    #pragma unroll
    for (int it = 0; it < 5; it++) {
        int e = tid + it*256;                 // float4 index 0..1151
        if (e < 18*64) {
            int r = e >> 6, q = e & 63;
            int gr = 2*i0 + r;
            float4 v = (gr < IMG) ? *(const float4*)&xb[gr*IMG + q*4] : make_float4(0,0,0,0);
            *(float4*)&xs[r*256 + q*4] = v;
        }
    }
    __syncthreads();
    #pragma unroll
    for (int p = 0; p < 4; p++) {
        int o = tid + p*256;
        if (o >= 8*HW) continue;              // 1016 outputs
        int r = o / HW, j = o - r*HW;
        int i = i0 + r;
        if (i >= HW) continue;
        const float* base = &xs[(2*r)*256 + 2*j];
        float acc = 0.f;
        #pragma unroll
        for (int dy = 0; dy < 4; dy++)
            #pragma unroll
            for (int dx = 0; dx < 4; dx++)
                acc += base[dy*256 + dx] * wr[dy*4 + dx];
        g_xd [(size_t)bc*SSP + i*HW + j] = acc;
        g_xdh[(size_t)bc*XDP + i*HW + j] = __float2half(acc);
    }
}

// ---------------- 2) bilinear downsample of attention_map -> g_a fp32 ----------------
__global__ __launch_bounds__(256) void resize_a_kernel(const float* __restrict__ am) {
    __shared__ float t[32][65];
    int b = blockIdx.z, i = blockIdx.y, j0 = blockIdx.x * 32;
    const float sc = 255.f / 126.f;
    float yf = i * sc; int y0 = (int)yf; float wy = yf - y0; int y1 = min(y0+1, IMG-1);
    #pragma unroll
    for (int it = 0; it < 8; it++) {
        int e = threadIdx.x + it*256;
        int ca = e >> 5, jj = e & 31;
        int j = j0 + jj;
        if (j < HW) {
            float xf = j * sc; int x0 = (int)xf; float wx = xf - x0; int x1 = min(x0+1, IMG-1);
            const float* P = am + ((size_t)(b*64 + ca)) * IMGSZ;
            float v = (P[y0*IMG+x0]*(1.f-wx) + P[y0*IMG+x1]*wx) * (1.f-wy)
                    + (P[y1*IMG+x0]*(1.f-wx) + P[y1*IMG+x1]*wx) * wy;
            t[jj][ca] = v;
        }
    }
    __syncthreads();
    #pragma unroll
    for (int it = 0; it < 8; it++) {
        int e = threadIdx.x + it*256;
        int jj = e >> 6, ca = e & 63;
        int j = j0 + jj;
        if (j < HW)
            g_a[((size_t)b*SSP + i*HW + j)*64 + ca] = t[jj][ca];
    }
}

// ---------------- 3) V projection (fp16 in, K-tile 64, fp16 out) ----------------
__global__ __launch_bounds__(256) void proj_v_kernel(const float* __restrict__ bias) {
    extern __shared__ __align__(16) float dsm[];
    float* As = dsm;             // [64][ASP]
    float* Bs = dsm + 64*ASP;    // [64][ASP]
    __shared__ float biass[128];
    int s0 = blockIdx.x * 128, n0 = blockIdx.y * 128, b = blockIdx.z;
    int tid = threadIdx.x, tx = tid & 15, ty = tid >> 4;
    unsigned long long acc[8][4] = {};
    const __half* Xh = g_xdh + (size_t)b * CC * XDP;
    if (tid < 128) biass[tid] = bias[n0 + tid];
    for (int k0 = 0; k0 < 256; k0 += 64) {
        #pragma unroll
        for (int i = 0; i < 4; i++) {
            int e = tid + i*256;
            int kk = e >> 4, g8 = e & 15;
            int sb = s0 + g8*8;
            uint4 u = make_uint4(0u,0u,0u,0u);
            if (sb < SSP) u = *(const uint4*)&Xh[(size_t)(k0+kk)*XDP + sb];
            const __half2* hp = (const __half2*)&u;
            float2 f0 = __half22float2(hp[0]);
            float2 f1 = __half22float2(hp[1]);
            float2 f2 = __half22float2(hp[2]);
            float2 f3 = __half22float2(hp[3]);
            float* d = &As[kk*ASP + g8*8];
            *(float4*)d     = make_float4(f0.x, f0.y, f1.x, f1.y);
            *(float4*)(d+4) = make_float4(f2.x, f2.y, f3.x, f3.y);
        }
        #pragma unroll
        for (int i = 0; i < 4; i++) {
            int e = tid + i*256;
            int nn = e >> 3, part = e & 7;
            uint4 u = *(const uint4*)&g_wvh[(size_t)(n0+nn)*256 + k0 + part*8];
            const __half2* hp = (const __half2*)&u;
            int kb = part*8;
            #pragma unroll
            for (int q = 0; q < 4; q++) {
                float2 f = __half22float2(hp[q]);
                Bs[(kb + q*2  )*ASP + nn] = f.x;
                Bs[(kb + q*2+1)*ASP + nn] = f.y;
            }
        }
        __syncthreads();
        #pragma unroll
        for (int q = 0; q < 4; q++)
            micro128(As + q*16*ASP, Bs + q*16*ASP, acc, tx, ty);
        __syncthreads();
    }
    int nb = n0 + ty*8;
    #pragma unroll
    for (int mi = 0; mi < 8; mi++) {
        int s = s0 + ((mi < 4) ? tx*4 + mi : 64 + tx*4 + mi - 4);
        if (s >= SSP) continue;
        float2 p0 = unpack2(acc[mi][0]), p1 = unpack2(acc[mi][1]);
        float2 p2 = unpack2(acc[mi][2]), p3 = unpack2(acc[mi][3]);
        __half2 q0 = __floats2half2_rn(p0.x + biass[ty*8+0], p0.y + biass[ty*8+1]);
        __half2 q1 = __floats2half2_rn(p1.x + biass[ty*8+2], p1.y + biass[ty*8+3]);
        __half2 q2 = __floats2half2_rn(p2.x + biass[ty*8+4], p2.y + biass[ty*8+5]);
        __half2 q3 = __floats2half2_rn(p3.x + biass[ty*8+6], p3.y + biass[ty*8+7]);
        uint4 u = make_uint4(*(uint32_t*)&q0, *(uint32_t*)&q1, *(uint32_t*)&q2, *(uint32_t*)&q3);
        *(uint4*)&g_vh[((size_t)b*SSP + s)*256 + nb] = u;
    }
}

// ---------------- 4) fused Q|K projection (fp16 in, K-tile 64, fp32 out — 82us verified) ----------------
__global__ __launch_bounds__(256) void proj_qk_kernel(const float* __restrict__ bq,
                                                      const float* __restrict__ bk) {
    extern __shared__ __align__(16) float dsm[];
    float* As = dsm;             // [64][ASP]
    float* Bs = dsm + 64*ASP;    // [64][68]
    int s0 = blockIdx.x * 128, b = blockIdx.y;
    int tid = threadIdx.x, tx = tid & 15, ty = tid >> 4;
    unsigned long long acc[8][2] = {};
    const __half* Xh = g_xdh + (size_t)b * CC * XDP;
    for (int k0 = 0; k0 < 256; k0 += 64) {
        #pragma unroll
        for (int i = 0; i < 4; i++) {
            int e = tid + i*256;
            int kk = e >> 4, g8 = e & 15;
            int sb = s0 + g8*8;
            uint4 u = make_uint4(0u,0u,0u,0u);
            if (sb < SSP) u = *(const uint4*)&Xh[(size_t)(k0+kk)*XDP + sb];
            const __half2* hp = (const __half2*)&u;
            float2 f0 = __half22float2(hp[0]);
            float2 f1 = __half22float2(hp[1]);
            float2 f2 = __half22float2(hp[2]);
            float2 f3 = __half22float2(hp[3]);
            float* d = &As[kk*ASP + g8*8];
            *(float4*)d     = make_float4(f0.x, f0.y, f1.x, f1.y);
            *(float4*)(d+4) = make_float4(f2.x, f2.y, f3.x, f3.y);
        }
        #pragma unroll
        for (int i = 0; i < 2; i++) {
            int e = tid + i*256;
            int nn = e >> 3, part = e & 7;
            uint4 u = *(const uint4*)&g_wqkh[(size_t)nn*256 + k0 + part*8];
            const __half2* hp = (const __half2*)&u;
            int kb = part*8;
            #pragma unroll
            for (int q = 0; q < 4; q++) {
                float2 f = __half22float2(hp[q]);
                Bs[(kb + q*2  )*68 + nn] = f.x;
                Bs[(kb + q*2+1)*68 + nn] = f.y;
            }
        }
        __syncthreads();
        #pragma unroll
        for (int q = 0; q < 4; q++)
            micro64(As + q*16*ASP, Bs + q*16*68, acc, tx, ty);
        __syncthreads();
    }
    int nb = ty*4;
    float bv[4];
    #pragma unroll
    for (int ni = 0; ni < 4; ni++) {
        int n = nb + ni;
        bv[ni] = (n < 32) ? bq[n] : bk[n-32];
    }
    #pragma unroll
    for (int mi = 0; mi < 8; mi++) {
        int s = s0 + ((mi < 4) ? tx*4 + mi : 64 + tx*4 + mi - 4);
        if (s >= SSP) continue;
        float2 p0 = unpack2(acc[mi][0]), p1 = unpack2(acc[mi][1]);
        *(float4*)&g_qk[((size_t)b*SSP + s)*64 + nb] =
            make_float4(p0.x+bv[0], p0.y+bv[1], p1.x+bv[2], p1.y+bv[3]);
    }
}

// ---------------- 5) energy store helper (fp16, H|W packed rows of 256) ----------------
__device__ __forceinline__ void energy_store(unsigned long long acc[8][4], __half* OUT,
                                             int b, int fix, int tx, int ty,
                                             bool modew, bool maskDiag) {
    const int noff = modew ? 128 : 0;
    #pragma unroll
    for (int mi = 0; mi < 8; mi++) {
        int m = (mi < 4) ? tx*4 + mi : 64 + tx*4 + mi - 4;
        if (m >= HW) continue;
        size_t row = modew ? ((size_t)(b*HW + fix)*HW + m) : ((size_t)(b*HW + m)*HW + fix);
        float v[8];
        #pragma unroll
        for (int np = 0; np < 4; np++) {
            float2 p = unpack2(acc[mi][np]);
            v[np*2] = p.x; v[np*2+1] = p.y;
        }
        #pragma unroll
        for (int ni = 0; ni < 8; ni++) {
            int n = ty*8 + ni;
            if (n == HW) v[ni] = -INFINITY;
            if (maskDiag && n == m) v[ni] = -INFINITY;
        }
        __half2 q0 = __floats2half2_rn(v[0], v[1]);
        __half2 q1 = __floats2half2_rn(v[2], v[3]);
        __half2 q2 = __floats2half2_rn(v[4], v[5]);
        __half2 q3 = __floats2half2_rn(v[6], v[7]);
        uint4 u = make_uint4(*(uint32_t*)&q0, *(uint32_t*)&q1, *(uint32_t*)&q2, *(uint32_t*)&q3);
        *(uint4*)&OUT[row*256 + noff + ty*8] = u;
    }
}

// ---------------- 6) e-energy (K=32, q.k) — R9 ----------------
template<bool MODEW>
__global__ __launch_bounds__(256) void energy_e_kernel() {
    __shared__ __align__(16) float As[32*ASP];
    __shared__ __align__(16) float Bs[32*ASP];
    int fix = blockIdx.x, b = blockIdx.y;
    int tid = threadIdx.x, tx = tid & 15, ty = tid >> 4;
    const float* S = g_qk + (size_t)b*SSP*64;
    #pragma unroll
    for (int i = 0; i < 16; i++) {
        int e = tid + i*256;
        int mm = e >> 5, kk = e & 31;
        int sp = MODEW ? fix*HW + mm : mm*HW + fix;
        float qa = 0.f, kb = 0.f;
        if (mm < HW) {
            qa = S[(size_t)sp*64 + kk];
            kb = S[(size_t)sp*64 + 32 + kk];
        }
        As[kk*ASP + mm] = qa;
        Bs[kk*ASP + mm] = kb;
    }
    __syncthreads();
    unsigned long long acc[8][4] = {};
    micro128(As, Bs, acc, tx, ty);
    micro128(As + 16*ASP, Bs + 16*ASP, acc, tx, ty);
    energy_store(acc, g_Eh, b, fix, tx, ty, MODEW, !MODEW);
}

// ---------------- 7) a-energy (K=64, symmetric a.a) — R9 ----------------
template<bool MODEW>
__global__ __launch_bounds__(256) void energy_a_kernel() {
    __shared__ __align__(16) float As[64*ASP];
    int fix = blockIdx.x, b = blockIdx.y;
    int tid = threadIdx.x, tx = tid & 15, ty = tid >> 4;
    const float* S = g_a + (size_t)b*SSP*64;
    #pragma unroll
    for (int i = 0; i < 32; i++) {
        int e = tid + i*256;
        int mm = e >> 6, kk = e & 63;
        int sp = MODEW ? fix*HW + mm : mm*HW + fix;
        As[kk*ASP + mm] = (mm < HW) ? S[(size_t)sp*64 + kk] : 0.f;
    }
    __syncthreads();
    unsigned long long acc[8][4] = {};
    #pragma unroll
    for (int q = 0; q < 4; q++)
        micro128(As + q*16*ASP, As + q*16*ASP, acc, tx, ty);
    energy_store(acc, g_Ah, b, fix, tx, ty, MODEW, !MODEW);
}

// ---------------- 8) fused triple softmax (fp16 in, fp16 S out) ----------------
__device__ __forceinline__ float wmax(float v) {
    #pragma unroll
    for (int o = 16; o; o >>= 1) v = fmaxf(v, __shfl_xor_sync(0xffffffffu, v, o));
    return v;
}
__device__ __forceinline__ float wsum(float v) {
    #pragma unroll
    for (int o = 16; o; o >>= 1) v += __shfl_xor_sync(0xffffffffu, v, o);
    return v;
}
__global__ __launch_bounds__(256) void softmax3_kernel() {
    int w = threadIdx.x >> 5, lane = threadIdx.x & 31;
    size_t row = (size_t)blockIdx.x * 8 + w;
    if (row >= (size_t)BB*SSP) return;
    uint4 eu = ((const uint4*)(g_Eh + row*256))[lane];
    uint4 au = ((const uint4*)(g_Ah + row*256))[lane];
    float ev[8], av[8];
    const __half2* ep = (const __half2*)&eu;
    const __half2* ap = (const __half2*)&au;
    #pragma unroll
    for (int i = 0; i < 4; i++) {
        float2 f = __half22float2(ep[i]); ev[2*i] = f.x; ev[2*i+1] = f.y;
        float2 g = __half22float2(ap[i]); av[2*i] = g.x; av[2*i+1] = g.y;
    }
    float m1 = -INFINITY, m2 = -INFINITY;
    #pragma unroll
    for (int i = 0; i < 8; i++) { m1 = fmaxf(m1, ev[i]); m2 = fmaxf(m2, av[i]); }
    m1 = wmax(m1); m2 = wmax(m2);
    float ce[8], ca[8], s1 = 0.f, s2 = 0.f;
    #pragma unroll
    for (int i = 0; i < 8; i++) {
        ce[i] = __expf(ev[i] - m1); s1 += ce[i];
        ca[i] = __expf(av[i] - m2); s2 += ca[i];
    }
    s1 = wsum(s1); s2 = wsum(s2);
    float r12 = 1.f / (s1 * s2);
    float pv[8];
    #pragma unroll
    for (int i = 0; i < 8; i++) pv[i] = ce[i] * ca[i] * r12;
    if (lane == 15 || lane == 31) pv[7] = -INFINITY;   // pad slots 127 / 255
    float m3 = -INFINITY;
    #pragma unroll
    for (int i = 0; i < 8; i++) m3 = fmaxf(m3, pv[i]);
    m3 = wmax(m3);
    float s3 = 0.f, ov[8];
    #pragma unroll
    for (int i = 0; i < 8; i++) { ov[i] = __expf(pv[i] - m3); s3 += ov[i]; }
    s3 = wsum(s3);
    float r3 = 1.f / s3;
    __half2 q0 = __floats2half2_rn(ov[0]*r3, ov[1]*r3);
    __half2 q1 = __floats2half2_rn(ov[2]*r3, ov[3]*r3);
    __half2 q2 = __floats2half2_rn(ov[4]*r3, ov[5]*r3);
    __half2 q3 = __floats2half2_rn(ov[6]*r3, ov[7]*r3);
    ((uint4*)(g_Sh + row*256))[lane] =
        make_uint4(*(uint32_t*)&q0, *(uint32_t*)&q1, *(uint32_t*)&q2, *(uint32_t*)&q3);
}

// ---------------- 9) out GEMMs (R14: K-tile 32, fp16 operands) -> fp16 ----------------
template<bool MODEW>
__global__ __launch_bounds__(256) void outgemm_kernel() {
    __shared__ __align__(16) float As[32*ASP];
    __shared__ __align__(16) float Bs[32*ASP];
    int fix = blockIdx.x, c0 = blockIdx.y*128, b = blockIdx.z;
    int tid = threadIdx.x, tx = tid & 15, ty = tid >> 4;
    const int noff = MODEW ? 128 : 0;
    unsigned long long acc[8][4] = {};
    for (int k0 = 0; k0 < 128; k0 += 32) {
        #pragma unroll
        for (int i = 0; i < 2; i++) {
            int e = tid + i*256;
            int kk = e >> 4, m8 = e & 15;
            int k = k0 + kk;
            float f[8];
            if (k < HW) {
                int sp = MODEW ? fix*HW + k : k*HW + fix;
                uint4 u = *(const uint4*)&g_vh[((size_t)b*SSP + sp)*256 + c0 + m8*8];
                const __half2* hp = (const __half2*)&u;
                #pragma unroll
                for (int q = 0; q < 4; q++) {
                    float2 t2 = __half22float2(hp[q]);
                    f[q*2] = t2.x; f[q*2+1] = t2.y;
                }
            } else {
                #pragma unroll
                for (int q = 0; q < 8; q++) f[q] = 0.f;
            }
            float* d = &As[kk*ASP + m8*8];
            *(float4*)d     = make_float4(f[0],f[1],f[2],f[3]);
            *(float4*)(d+4) = make_float4(f[4],f[5],f[6],f[7]);
        }
        #pragma unroll
        for (int i = 0; i < 2; i++) {
            int e = tid + i*256;
            int nn = e >> 2, ko = e & 3;
            float f[8];
            if (nn < HW) {
                size_t srow = MODEW ? ((size_t)(b*HW+fix)*HW + nn) : ((size_t)(b*HW+nn)*HW + fix);
                uint4 u = *(const uint4*)&g_Sh[srow*256 + noff + k0 + ko*8];
                const __half2* hp = (const __half2*)&u;
                #pragma unroll
                for (int q = 0; q < 4; q++) {
                    float2 t2 = __half22float2(hp[q]);
                    f[q*2] = t2.x; f[q*2+1] = t2.y;
                }
            } else {
                #pragma unroll
                for (int q = 0; q < 8; q++) f[q] = 0.f;
            }
            #pragma unroll
            for (int t = 0; t < 8; t++) {
                int k = k0 + ko*8 + t;
                Bs[(ko*8 + t)*ASP + nn] = (k < HW) ? f[t] : 0.f;
            }
        }
        __syncthreads();
        micro128(As, Bs, acc, tx, ty);
        micro128(As + 16*ASP, Bs + 16*ASP, acc, tx, ty);
        __syncthreads();
    }
    __half* O = MODEW ? g_oW : g_oH;
    #pragma unroll
    for (int mi = 0; mi < 8; mi++) {
        int c = c0 + ((mi < 4) ? tx*4 + mi : 64 + tx*4 + mi - 4);
        float v[8];
        #pragma unroll
        for (int np = 0; np < 4; np++) {
            float2 p = unpack2(acc[mi][np]);
            v[np*2] = p.x; v[np*2+1] = p.y;
        }
        __half2 q0 = __floats2half2_rn(v[0], v[1]);
        __half2 q1 = __floats2half2_rn(v[2], v[3]);
        __half2 q2 = __floats2half2_rn(v[4], v[5]);
        __half2 q3 = __floats2half2_rn(v[6], v[7]);
        uint4 u = make_uint4(*(uint32_t*)&q0, *(uint32_t*)&q1, *(uint32_t*)&q2, *(uint32_t*)&q3);
        *(uint4*)&O[((size_t)(b*256 + c)*HW + fix)*128 + ty*8] = u;
    }
}

// ---------------- 10) bilinear upsample 127->256, residual ----------------
__global__ __launch_bounds__(256) void final_kernel(const float* __restrict__ x,
                                                    const float* __restrict__ gamma,
                                                    float* __restrict__ out) {
    int bc = blockIdx.z;
    int xx = blockIdx.x * 32 + (threadIdx.x & 31);
    int yy = blockIdx.y * 8  + (threadIdx.x >> 5);
    const float sc = 126.f / 255.f;
    float yf = yy * sc; int y0 = (int)yf; float wy = yf - y0; int y1 = min(y0+1, HW-1);
    float xf = xx * sc; int x0 = (int)xf; float wx = xf - x0; int x1 = min(x0+1, HW-1);
    const __half* Ht = g_oH + (size_t)bc * HW * 128;   // [j][i]
    const __half* Wt = g_oW + (size_t)bc * HW * 128;   // [i][j]
    float h00 = __half2float(Ht[x0*128 + y0]), h01 = __half2float(Ht[x0*128 + y1]);
    float h10 = __half2float(Ht[x1*128 + y0]), h11 = __half2float(Ht[x1*128 + y1]);
    float hv = (h00*(1.f-wy) + h01*wy)*(1.f-wx) + (h10*(1.f-wy) + h11*wy)*wx;
    float w00 = __half2float(Wt[y0*128 + x0]), w01 = __half2float(Wt[y0*128 + x1]);
    float w10 = __half2float(Wt[y1*128 + x0]), w11 = __half2float(Wt[y1*128 + x1]);
    float wv = (w00*(1.f-wx) + w01*wx)*(1.f-wy) + (w10*(1.f-wx) + w11*wx)*wy;
    size_t idx = (size_t)bc * IMGSZ + yy*IMG + xx;
    out[idx] = gamma[0] * (hv + wv) + x[idx];
}

// ---------------- launch ----------------
extern "C" void kernel_launch(void* const* d_in, const int* in_sizes, int n_in,
                              void* d_out, int out_size) {
    (void)in_sizes; (void)n_in; (void)out_size;
    const float* x  = (const float*)d_in[0];
    const float* am = (const float*)d_in[1];
    const float* wd = (const float*)d_in[2];
    const float* wq = (const float*)d_in[3];
    const float* bq = (const float*)d_in[4];
    const float* wk = (const float*)d_in[5];
    const float* bk = (const float*)d_in[6];
    const float* wv = (const float*)d_in[7];
    const float* bv = (const float*)d_in[8];
    const float* gm = (const float*)d_in[9];
    float* out = (float*)d_out;

    const int SM_QK = 64*ASP*4 + 64*68*4;    // 51200
    const int SM_V  = 2*64*ASP*4;            // 67584
    cudaFuncSetAttribute(proj_qk_kernel, cudaFuncAttributeMaxDynamicSharedMemorySize, SM_QK);
    cudaFuncSetAttribute(proj_v_kernel,  cudaFuncAttributeMaxDynamicSharedMemorySize, SM_V);

    prep_w_kernel<<<320, 256>>>(wq, wk, wv);
    conv_down_kernel<<<dim3(BB*CC, 16), 256>>>(x, wd);
    resize_a_kernel<<<dim3(4, HW, BB), 256>>>(am);

    proj_qk_kernel<<<dim3(127, BB), 256, SM_QK>>>(bq, bk);
    proj_v_kernel<<<dim3(127, 2, BB), 256, SM_V>>>(bv);

    energy_e_kernel<false><<<dim3(HW, BB), 256>>>();  // eH (masked)
    energy_e_kernel<true ><<<dim3(HW, BB), 256>>>();  // eW
    energy_a_kernel<false><<<dim3(HW, BB), 256>>>();  // aH (masked)
    energy_a_kernel<true ><<<dim3(HW, BB), 256>>>();  // aW

    softmax3_kernel<<<(BB*SSP + 7)/8, 256>>>();

    outgemm_kernel<false><<<dim3(HW, 2, BB), 256>>>();
    outgemm_kernel<true ><<<dim3(HW, 2, BB), 256>>>();

    final_kernel<<<dim3(8, 32, BB*CC), 256>>>(x, gm, out);
}

// round 17
// speedup vs baseline: 1.0765x; 1.0765x over previous
#include <cuda_runtime.h>
#include <cuda_fp16.h>
#include <math.h>
#include <stdint.h>

#define SSP 16129   // 127*127
#define XDP 16136   // padded fp16 xd row stride (16B-aligned rows)
#define HW  127
#define BB  4
#define CC  256
#define IMG 256
#define IMGSZ 65536
#define ASP 132

// ---------------- scratch (device globals; no allocation) ----------------
__device__ __align__(16) __half g_xdh[(size_t)BB*CC*XDP];   // downsampled x fp16 [b][c][s(pad)]
__device__ float g_qk[(size_t)BB*SSP*64];                   // q(0..31)|k(32..63) fp32 [b][s][64]
__device__ float g_a [(size_t)BB*SSP*64];                   // resized attn fp32 [b][s][64]
__device__ __align__(16) __half g_wqkh[64*256];             // wq|wk fp16
__device__ __align__(16) __half g_wvh[256*256];             // wv fp16
__device__ __align__(16) __half g_Eh[(size_t)BB*SSP*256];   // energies fp16 (rows of 256: H|W)
__device__ __align__(16) __half g_Ah[(size_t)BB*SSP*256];   // a-energies fp16
__device__ __align__(16) __half g_Sh[(size_t)BB*SSP*256];   // softmax S fp16
__device__ __align__(16) __half g_vh[(size_t)BB*SSP*256];   // v fp16 [b][s][256]
__device__ __align__(16) __half g_oH[(size_t)BB*CC*HW*128]; // outH [b][c][j][i(pad128)]
__device__ __align__(16) __half g_oW[(size_t)BB*CC*HW*128]; // outW [b][c][i][j(pad128)]

// ---------------- f32x2 helpers ----------------
__device__ __forceinline__ unsigned long long dup2(float x) {
    unsigned long long r;
    asm("mov.b64 %0, {%1, %1};" : "=l"(r) : "f"(x));
    return r;
}
__device__ __forceinline__ void fma2(unsigned long long& d, unsigned long long a, unsigned long long b) {
    asm("fma.rn.f32x2 %0, %1, %2, %0;" : "+l"(d) : "l"(a), "l"(b));
}
__device__ __forceinline__ float2 unpack2(unsigned long long v) {
    float2 r;
    asm("mov.b64 {%0, %1}, %2;" : "=f"(r.x), "=f"(r.y) : "l"(v));
    return r;
}

// R2 broadcast microkernels. As/Bs: [16][stride] floats (m/n contiguous).
__device__ __forceinline__ void micro128(const float* As, const float* Bs,
                                         unsigned long long acc[8][4], int tx, int ty) {
    #pragma unroll
    for (int kk = 0; kk < 16; kk++) {
        float4 x0 = *(const float4*)&As[kk*ASP + tx*4];
        float4 x1 = *(const float4*)&As[kk*ASP + 64 + tx*4];
        ulonglong2 w0 = *(const ulonglong2*)&Bs[kk*ASP + ty*8];
        ulonglong2 w1 = *(const ulonglong2*)&Bs[kk*ASP + ty*8 + 4];
        unsigned long long xs[8];
        xs[0]=dup2(x0.x); xs[1]=dup2(x0.y); xs[2]=dup2(x0.z); xs[3]=dup2(x0.w);
        xs[4]=dup2(x1.x); xs[5]=dup2(x1.y); xs[6]=dup2(x1.z); xs[7]=dup2(x1.w);
        #pragma unroll
        for (int m = 0; m < 8; m++) {
            fma2(acc[m][0], xs[m], w0.x);
            fma2(acc[m][1], xs[m], w0.y);
            fma2(acc[m][2], xs[m], w1.x);
            fma2(acc[m][3], xs[m], w1.y);
        }
    }
}
__device__ __forceinline__ void micro64(const float* As, const float* Bs,
                                        unsigned long long acc[8][2], int tx, int ty) {
    #pragma unroll
    for (int kk = 0; kk < 16; kk++) {
        float4 x0 = *(const float4*)&As[kk*ASP + tx*4];
        float4 x1 = *(const float4*)&As[kk*ASP + 64 + tx*4];
        ulonglong2 w0 = *(const ulonglong2*)&Bs[kk*68 + ty*4];
        unsigned long long xs[8];
        xs[0]=dup2(x0.x); xs[1]=dup2(x0.y); xs[2]=dup2(x0.z); xs[3]=dup2(x0.w);
        xs[4]=dup2(x1.x); xs[5]=dup2(x1.y); xs[6]=dup2(x1.z); xs[7]=dup2(x1.w);
        #pragma unroll
        for (int m = 0; m < 8; m++) {
            fma2(acc[m][0], xs[m], w0.x);
            fma2(acc[m][1], xs[m], w0.y);
        }
    }
}

// ---------------- 0) weight prep: wq|wk and wv fp32 -> fp16 ----------------
__global__ void prep_w_kernel(const float* __restrict__ wq, const float* __restrict__ wk,
                              const float* __restrict__ wv) {
    int idx = blockIdx.x * 256 + threadIdx.x;   // 320 blocks
    if (idx < 64*256) {
        int n = idx >> 8, k = idx & 255;
        float v = (n < 32) ? wq[n*256 + k] : wk[(n-32)*256 + k];
        g_wqkh[idx] = __float2half(v);
    } else {
        int e = idx - 64*256;                   // 0 .. 65535
        g_wvh[e] = __float2half(wv[e]);
    }
}

// ---------------- 1) depthwise 4x4 stride-2 conv — smem-tiled, fp16 out only ----------------
__global__ __launch_bounds__(256) void conv_down_kernel(const float* __restrict__ x,
                                                        const float* __restrict__ wd) {
    __shared__ __align__(16) float xs[18*256];
    int bc = blockIdx.x;            // b*256 + c
    int i0 = blockIdx.y * 8;
    int c  = bc & 255;
    int tid = threadIdx.x;
    float wr[16];
    #pragma unroll
    for (int t = 0; t < 16; t++) wr[t] = wd[c*16 + t];
    const float* xb = x + (size_t)bc * IMGSZ;
    #pragma unroll
    for (int it = 0; it < 5; it++) {
        int e = tid + it*256;                 // float4 index 0..1151
        if (e < 18*64) {
            int r = e >> 6, q = e & 63;
            int gr = 2*i0 + r;
            float4 v = (gr < IMG) ? *(const float4*)&xb[gr*IMG + q*4] : make_float4(0,0,0,0);
            *(float4*)&xs[r*256 + q*4] = v;
        }
    }
    __syncthreads();
    #pragma unroll
    for (int p = 0; p < 4; p++) {
        int o = tid + p*256;
        if (o >= 8*HW) continue;              // 1016 outputs
        int r = o / HW, j = o - r*HW;
        int i = i0 + r;
        if (i >= HW) continue;
        const float* base = &xs[(2*r)*256 + 2*j];
        float acc = 0.f;
        #pragma unroll
        for (int dy = 0; dy < 4; dy++)
            #pragma unroll
            for (int dx = 0; dx < 4; dx++)
                acc += base[dy*256 + dx] * wr[dy*4 + dx];
        g_xdh[(size_t)bc*XDP + i*HW + j] = __float2half(acc);
    }
}

// ---------------- 2) bilinear downsample of attention_map -> g_a fp32 ----------------
__global__ __launch_bounds__(256) void resize_a_kernel(const float* __restrict__ am) {
    __shared__ float t[32][65];
    int b = blockIdx.z, i = blockIdx.y, j0 = blockIdx.x * 32;
    const float sc = 255.f / 126.f;
    float yf = i * sc; int y0 = (int)yf; float wy = yf - y0; int y1 = min(y0+1, IMG-1);
    #pragma unroll
    for (int it = 0; it < 8; it++) {
        int e = threadIdx.x + it*256;
        int ca = e >> 5, jj = e & 31;
        int j = j0 + jj;
        if (j < HW) {
            float xf = j * sc; int x0 = (int)xf; float wx = xf - x0; int x1 = min(x0+1, IMG-1);
            const float* P = am + ((size_t)(b*64 + ca)) * IMGSZ;
            float v = (P[y0*IMG+x0]*(1.f-wx) + P[y0*IMG+x1]*wx) * (1.f-wy)
                    + (P[y1*IMG+x0]*(1.f-wx) + P[y1*IMG+x1]*wx) * wy;
            t[jj][ca] = v;
        }
    }
    __syncthreads();
    #pragma unroll
    for (int it = 0; it < 8; it++) {
        int e = threadIdx.x + it*256;
        int jj = e >> 6, ca = e & 63;
        int j = j0 + jj;
        if (j < HW)
            g_a[((size_t)b*SSP + i*HW + j)*64 + ca] = t[jj][ca];
    }
}

// ---------------- 3) V projection (fp16 in, K-tile 32, fp16 out) ----------------
__global__ __launch_bounds__(256) void proj_v_kernel(const float* __restrict__ bias) {
    __shared__ __align__(16) float As[32*ASP];
    __shared__ __align__(16) float Bs[32*ASP];
    __shared__ float biass[128];
    int s0 = blockIdx.x * 128, n0 = blockIdx.y * 128, b = blockIdx.z;
    int tid = threadIdx.x, tx = tid & 15, ty = tid >> 4;
    unsigned long long acc[8][4] = {};
    const __half* Xh = g_xdh + (size_t)b * CC * XDP;
    if (tid < 128) biass[tid] = bias[n0 + tid];
    for (int k0 = 0; k0 < 256; k0 += 32) {
        // A: 32 k-rows x 128 m halves (uint4 = 8 halves)
        #pragma unroll
        for (int i = 0; i < 2; i++) {
            int e = tid + i*256;
            int kk = e >> 4, g8 = e & 15;
            int sb = s0 + g8*8;
            uint4 u = make_uint4(0u,0u,0u,0u);
            if (sb < SSP) u = *(const uint4*)&Xh[(size_t)(k0+kk)*XDP + sb];
            const __half2* hp = (const __half2*)&u;
            float2 f0 = __half22float2(hp[0]);
            float2 f1 = __half22float2(hp[1]);
            float2 f2 = __half22float2(hp[2]);
            float2 f3 = __half22float2(hp[3]);
            float* d = &As[kk*ASP + g8*8];
            *(float4*)d     = make_float4(f0.x, f0.y, f1.x, f1.y);
            *(float4*)(d+4) = make_float4(f2.x, f2.y, f3.x, f3.y);
        }
        // B: 128 n-rows x 32 k halves (uint4 = 8 halves), transpose into [kk][nn]
        #pragma unroll
        for (int i = 0; i < 2; i++) {
            int e = tid + i*256;
            int nn = e >> 2, part = e & 3;
            uint4 u = *(const uint4*)&g_wvh[(size_t)(n0+nn)*256 + k0 + part*8];
            const __half2* hp = (const __half2*)&u;
            int kb = part*8;
            #pragma unroll
            for (int q = 0; q < 4; q++) {
                float2 f = __half22float2(hp[q]);
                Bs[(kb + q*2  )*ASP + nn] = f.x;
                Bs[(kb + q*2+1)*ASP + nn] = f.y;
            }
        }
        __syncthreads();
        micro128(As, Bs, acc, tx, ty);
        micro128(As + 16*ASP, Bs + 16*ASP, acc, tx, ty);
        __syncthreads();
    }
    int nb = n0 + ty*8;
    #pragma unroll
    for (int mi = 0; mi < 8; mi++) {
        int s = s0 + ((mi < 4) ? tx*4 + mi : 64 + tx*4 + mi - 4);
        if (s >= SSP) continue;
        float2 p0 = unpack2(acc[mi][0]), p1 = unpack2(acc[mi][1]);
        float2 p2 = unpack2(acc[mi][2]), p3 = unpack2(acc[mi][3]);
        __half2 q0 = __floats2half2_rn(p0.x + biass[ty*8+0], p0.y + biass[ty*8+1]);
        __half2 q1 = __floats2half2_rn(p1.x + biass[ty*8+2], p1.y + biass[ty*8+3]);
        __half2 q2 = __floats2half2_rn(p2.x + biass[ty*8+4], p2.y + biass[ty*8+5]);
        __half2 q3 = __floats2half2_rn(p3.x + biass[ty*8+6], p3.y + biass[ty*8+7]);
        uint4 u = make_uint4(*(uint32_t*)&q0, *(uint32_t*)&q1, *(uint32_t*)&q2, *(uint32_t*)&q3);
        *(uint4*)&g_vh[((size_t)b*SSP + s)*256 + nb] = u;
    }
}

// ---------------- 4) fused Q|K projection (fp16 in, K-tile 64, fp32 out — 82us verified) ----------------
__global__ __launch_bounds__(256) void proj_qk_kernel(const float* __restrict__ bq,
                                                      const float* __restrict__ bk) {
    extern __shared__ __align__(16) float dsm[];
    float* As = dsm;             // [64][ASP]
    float* Bs = dsm + 64*ASP;    // [64][68]
    int s0 = blockIdx.x * 128, b = blockIdx.y;
    int tid = threadIdx.x, tx = tid & 15, ty = tid >> 4;
    unsigned long long acc[8][2] = {};
    const __half* Xh = g_xdh + (size_t)b * CC * XDP;
    for (int k0 = 0; k0 < 256; k0 += 64) {
        #pragma unroll
        for (int i = 0; i < 4; i++) {
            int e = tid + i*256;
            int kk = e >> 4, g8 = e & 15;
            int sb = s0 + g8*8;
            uint4 u = make_uint4(0u,0u,0u,0u);
            if (sb < SSP) u = *(const uint4*)&Xh[(size_t)(k0+kk)*XDP + sb];
            const __half2* hp = (const __half2*)&u;
            float2 f0 = __half22float2(hp[0]);
            float2 f1 = __half22float2(hp[1]);
            float2 f2 = __half22float2(hp[2]);
            float2 f3 = __half22float2(hp[3]);
            float* d = &As[kk*ASP + g8*8];
            *(float4*)d     = make_float4(f0.x, f0.y, f1.x, f1.y);
            *(float4*)(d+4) = make_float4(f2.x, f2.y, f3.x, f3.y);
        }
        #pragma unroll
        for (int i = 0; i < 2; i++) {
            int e = tid + i*256;
            int nn = e >> 3, part = e & 7;
            uint4 u = *(const uint4*)&g_wqkh[(size_t)nn*256 + k0 + part*8];
            const __half2* hp = (const __half2*)&u;
            int kb = part*8;
            #pragma unroll
            for (int q = 0; q < 4; q++) {
                float2 f = __half22float2(hp[q]);
                Bs[(kb + q*2  )*68 + nn] = f.x;
                Bs[(kb + q*2+1)*68 + nn] = f.y;
            }
        }
        __syncthreads();
        #pragma unroll
        for (int q = 0; q < 4; q++)
            micro64(As + q*16*ASP, Bs + q*16*68, acc, tx, ty);
        __syncthreads();
    }
    int nb = ty*4;
    float bv[4];
    #pragma unroll
    for (int ni = 0; ni < 4; ni++) {
        int n = nb + ni;
        bv[ni] = (n < 32) ? bq[n] : bk[n-32];
    }
    #pragma unroll
    for (int mi = 0; mi < 8; mi++) {
        int s = s0 + ((mi < 4) ? tx*4 + mi : 64 + tx*4 + mi - 4);
        if (s >= SSP) continue;
        float2 p0 = unpack2(acc[mi][0]), p1 = unpack2(acc[mi][1]);
        *(float4*)&g_qk[((size_t)b*SSP + s)*64 + nb] =
            make_float4(p0.x+bv[0], p0.y+bv[1], p1.x+bv[2], p1.y+bv[3]);
    }
}

// ---------------- 5) energy store helper (fp16, H|W packed rows of 256) ----------------
__device__ __forceinline__ void energy_store(unsigned long long acc[8][4], __half* OUT,
                                             int b, int fix, int tx, int ty,
                                             bool modew, bool maskDiag) {
    const int noff = modew ? 128 : 0;
    #pragma unroll
    for (int mi = 0; mi < 8; mi++) {
        int m = (mi < 4) ? tx*4 + mi : 64 + tx*4 + mi - 4;
        if (m >= HW) continue;
        size_t row = modew ? ((size_t)(b*HW + fix)*HW + m) : ((size_t)(b*HW + m)*HW + fix);
        float v[8];
        #pragma unroll
        for (int np = 0; np < 4; np++) {
            float2 p = unpack2(acc[mi][np]);
            v[np*2] = p.x; v[np*2+1] = p.y;
        }
        #pragma unroll
        for (int ni = 0; ni < 8; ni++) {
            int n = ty*8 + ni;
            if (n == HW) v[ni] = -INFINITY;
            if (maskDiag && n == m) v[ni] = -INFINITY;
        }
        __half2 q0 = __floats2half2_rn(v[0], v[1]);
        __half2 q1 = __floats2half2_rn(v[2], v[3]);
        __half2 q2 = __floats2half2_rn(v[4], v[5]);
        __half2 q3 = __floats2half2_rn(v[6], v[7]);
        uint4 u = make_uint4(*(uint32_t*)&q0, *(uint32_t*)&q1, *(uint32_t*)&q2, *(uint32_t*)&q3);
        *(uint4*)&OUT[row*256 + noff + ty*8] = u;
    }
}

// ---------------- 6) e-energy (K=32, q.k) — R9 ----------------
template<bool MODEW>
__global__ __launch_bounds__(256) void energy_e_kernel() {
    __shared__ __align__(16) float As[32*ASP];
    __shared__ __align__(16) float Bs[32*ASP];
    int fix = blockIdx.x, b = blockIdx.y;
    int tid = threadIdx.x, tx = tid & 15, ty = tid >> 4;
    const float* S = g_qk + (size_t)b*SSP*64;
    #pragma unroll
    for (int i = 0; i < 16; i++) {
        int e = tid + i*256;
        int mm = e >> 5, kk = e & 31;
        int sp = MODEW ? fix*HW + mm : mm*HW + fix;
        float qa = 0.f, kb = 0.f;
        if (mm < HW) {
            qa = S[(size_t)sp*64 + kk];
            kb = S[(size_t)sp*64 + 32 + kk];
        }
        As[kk*ASP + mm] = qa;
        Bs[kk*ASP + mm] = kb;
    }
    __syncthreads();
    unsigned long long acc[8][4] = {};
    micro128(As, Bs, acc, tx, ty);
    micro128(As + 16*ASP, Bs + 16*ASP, acc, tx, ty);
    energy_store(acc, g_Eh, b, fix, tx, ty, MODEW, !MODEW);
}

// ---------------- 7) a-energy (K=64, symmetric a.a) — R9 ----------------
template<bool MODEW>
__global__ __launch_bounds__(256) void energy_a_kernel() {
    __shared__ __align__(16) float As[64*ASP];
    int fix = blockIdx.x, b = blockIdx.y;
    int tid = threadIdx.x, tx = tid & 15, ty = tid >> 4;
    const float* S = g_a + (size_t)b*SSP*64;
    #pragma unroll
    for (int i = 0; i < 32; i++) {
        int e = tid + i*256;
        int mm = e >> 6, kk = e & 63;
        int sp = MODEW ? fix*HW + mm : mm*HW + fix;
        As[kk*ASP + mm] = (mm < HW) ? S[(size_t)sp*64 + kk] : 0.f;
    }
    __syncthreads();
    unsigned long long acc[8][4] = {};
    #pragma unroll
    for (int q = 0; q < 4; q++)
        micro128(As + q*16*ASP, As + q*16*ASP, acc, tx, ty);
    energy_store(acc, g_Ah, b, fix, tx, ty, MODEW, !MODEW);
}

// ---------------- 8) fused triple softmax (fp16 in, fp16 S out) ----------------
__device__ __forceinline__ float wmax(float v) {
    #pragma unroll
    for (int o = 16; o; o >>= 1) v = fmaxf(v, __shfl_xor_sync(0xffffffffu, v, o));
    return v;
}
__device__ __forceinline__ float wsum(float v) {
    #pragma unroll
    for (int o = 16; o; o >>= 1) v += __shfl_xor_sync(0xffffffffu, v, o);
    return v;
}
__global__ __launch_bounds__(256) void softmax3_kernel() {
    int w = threadIdx.x >> 5, lane = threadIdx.x & 31;
    size_t row = (size_t)blockIdx.x * 8 + w;
    if (row >= (size_t)BB*SSP) return;
    uint4 eu = ((const uint4*)(g_Eh + row*256))[lane];
    uint4 au = ((const uint4*)(g_Ah + row*256))[lane];
    float ev[8], av[8];
    const __half2* ep = (const __half2*)&eu;
    const __half2* ap = (const __half2*)&au;
    #pragma unroll
    for (int i = 0; i < 4; i++) {
        float2 f = __half22float2(ep[i]); ev[2*i] = f.x; ev[2*i+1] = f.y;
        float2 g = __half22float2(ap[i]); av[2*i] = g.x; av[2*i+1] = g.y;
    }
    float m1 = -INFINITY, m2 = -INFINITY;
    #pragma unroll
    for (int i = 0; i < 8; i++) { m1 = fmaxf(m1, ev[i]); m2 = fmaxf(m2, av[i]); }
    m1 = wmax(m1); m2 = wmax(m2);
    float ce[8], ca[8], s1 = 0.f, s2 = 0.f;
    #pragma unroll
    for (int i = 0; i < 8; i++) {
        ce[i] = __expf(ev[i] - m1); s1 += ce[i];
        ca[i] = __expf(av[i] - m2); s2 += ca[i];
    }
    s1 = wsum(s1); s2 = wsum(s2);
    float r12 = 1.f / (s1 * s2);
    float pv[8];
    #pragma unroll
    for (int i = 0; i < 8; i++) pv[i] = ce[i] * ca[i] * r12;
    if (lane == 15 || lane == 31) pv[7] = -INFINITY;   // pad slots 127 / 255
    float m3 = -INFINITY;
    #pragma unroll
    for (int i = 0; i < 8; i++) m3 = fmaxf(m3, pv[i]);
    m3 = wmax(m3);
    float s3 = 0.f, ov[8];
    #pragma unroll
    for (int i = 0; i < 8; i++) { ov[i] = __expf(pv[i] - m3); s3 += ov[i]; }
    s3 = wsum(s3);
    float r3 = 1.f / s3;
    __half2 q0 = __floats2half2_rn(ov[0]*r3, ov[1]*r3);
    __half2 q1 = __floats2half2_rn(ov[2]*r3, ov[3]*r3);
    __half2 q2 = __floats2half2_rn(ov[4]*r3, ov[5]*r3);
    __half2 q3 = __floats2half2_rn(ov[6]*r3, ov[7]*r3);
    ((uint4*)(g_Sh + row*256))[lane] =
        make_uint4(*(uint32_t*)&q0, *(uint32_t*)&q1, *(uint32_t*)&q2, *(uint32_t*)&q3);
}

// ---------------- 9) out GEMMs (R14: K-tile 32, fp16 operands) -> fp16 ----------------
template<bool MODEW>
__global__ __launch_bounds__(256) void outgemm_kernel() {
    __shared__ __align__(16) float As[32*ASP];
    __shared__ __align__(16) float Bs[32*ASP];
    int fix = blockIdx.x, c0 = blockIdx.y*128, b = blockIdx.z;
    int tid = threadIdx.x, tx = tid & 15, ty = tid >> 4;
    const int noff = MODEW ? 128 : 0;
    unsigned long long acc[8][4] = {};
    for (int k0 = 0; k0 < 128; k0 += 32) {
        #pragma unroll
        for (int i = 0; i < 2; i++) {
            int e = tid + i*256;
            int kk = e >> 4, m8 = e & 15;
            int k = k0 + kk;
            float f[8];
            if (k < HW) {
                int sp = MODEW ? fix*HW + k : k*HW + fix;
                uint4 u = *(const uint4*)&g_vh[((size_t)b*SSP + sp)*256 + c0 + m8*8];
                const __half2* hp = (const __half2*)&u;
                #pragma unroll
                for (int q = 0; q < 4; q++) {
                    float2 t2 = __half22float2(hp[q]);
                    f[q*2] = t2.x; f[q*2+1] = t2.y;
                }
            } else {
                #pragma unroll
                for (int q = 0; q < 8; q++) f[q] = 0.f;
            }
            float* d = &As[kk*ASP + m8*8];
            *(float4*)d     = make_float4(f[0],f[1],f[2],f[3]);
            *(float4*)(d+4) = make_float4(f[4],f[5],f[6],f[7]);
        }
        #pragma unroll
        for (int i = 0; i < 2; i++) {
            int e = tid + i*256;
            int nn = e >> 2, ko = e & 3;
            float f[8];
            if (nn < HW) {
                size_t srow = MODEW ? ((size_t)(b*HW+fix)*HW + nn) : ((size_t)(b*HW+nn)*HW + fix);
                uint4 u = *(const uint4*)&g_Sh[srow*256 + noff + k0 + ko*8];
                const __half2* hp = (const __half2*)&u;
                #pragma unroll
                for (int q = 0; q < 4; q++) {
                    float2 t2 = __half22float2(hp[q]);
                    f[q*2] = t2.x; f[q*2+1] = t2.y;
                }
            } else {
                #pragma unroll
                for (int q = 0; q < 8; q++) f[q] = 0.f;
            }
            #pragma unroll
            for (int t = 0; t < 8; t++) {
                int k = k0 + ko*8 + t;
                Bs[(ko*8 + t)*ASP + nn] = (k < HW) ? f[t] : 0.f;
            }
        }
        __syncthreads();
        micro128(As, Bs, acc, tx, ty);
        micro128(As + 16*ASP, Bs + 16*ASP, acc, tx, ty);
        __syncthreads();
    }
    __half* O = MODEW ? g_oW : g_oH;
    #pragma unroll
    for (int mi = 0; mi < 8; mi++) {
        int c = c0 + ((mi < 4) ? tx*4 + mi : 64 + tx*4 + mi - 4);
        float v[8];
        #pragma unroll
        for (int np = 0; np < 4; np++) {
            float2 p = unpack2(acc[mi][np]);
            v[np*2] = p.x; v[np*2+1] = p.y;
        }
        __half2 q0 = __floats2half2_rn(v[0], v[1]);
        __half2 q1 = __floats2half2_rn(v[2], v[3]);
        __half2 q2 = __floats2half2_rn(v[4], v[5]);
        __half2 q3 = __floats2half2_rn(v[6], v[7]);
        uint4 u = make_uint4(*(uint32_t*)&q0, *(uint32_t*)&q1, *(uint32_t*)&q2, *(uint32_t*)&q3);
        *(uint4*)&O[((size_t)(b*256 + c)*HW + fix)*128 + ty*8] = u;
    }
}

// ---------------- 10) bilinear upsample 127->256, residual ----------------
__global__ __launch_bounds__(256) void final_kernel(const float* __restrict__ x,
                                                    const float* __restrict__ gamma,
                                                    float* __restrict__ out) {
    int bc = blockIdx.z;
    int xx = blockIdx.x * 32 + (threadIdx.x & 31);
    int yy = blockIdx.y * 8  + (threadIdx.x >> 5);
    const float sc = 126.f / 255.f;
    float yf = yy * sc; int y0 = (int)yf; float wy = yf - y0; int y1 = min(y0+1, HW-1);
    float xf = xx * sc; int x0 = (int)xf; float wx = xf - x0; int x1 = min(x0+1, HW-1);
    const __half* Ht = g_oH + (size_t)bc * HW * 128;   // [j][i]
    const __half* Wt = g_oW + (size_t)bc * HW * 128;   // [i][j]
    float h00 = __half2float(Ht[x0*128 + y0]), h01 = __half2float(Ht[x0*128 + y1]);
    float h10 = __half2float(Ht[x1*128 + y0]), h11 = __half2float(Ht[x1*128 + y1]);
    float hv = (h00*(1.f-wy) + h01*wy)*(1.f-wx) + (h10*(1.f-wy) + h11*wy)*wx;
    float w00 = __half2float(Wt[y0*128 + x0]), w01 = __half2float(Wt[y0*128 + x1]);
    float w10 = __half2float(Wt[y1*128 + x0]), w11 = __half2float(Wt[y1*128 + x1]);
    float wv = (w00*(1.f-wx) + w01*wx)*(1.f-wy) + (w10*(1.f-wx) + w11*wx)*wy;
    size_t idx = (size_t)bc * IMGSZ + yy*IMG + xx;
    out[idx] = gamma[0] * (hv + wv) + x[idx];
}

// ---------------- launch ----------------
extern "C" void kernel_launch(void* const* d_in, const int* in_sizes, int n_in,
                              void* d_out, int out_size) {
    (void)in_sizes; (void)n_in; (void)out_size;
    const float* x  = (const float*)d_in[0];
    const float* am = (const float*)d_in[1];
    const float* wd = (const float*)d_in[2];
    const float* wq = (const float*)d_in[3];
    const float* bq = (const float*)d_in[4];
    const float* wk = (const float*)d_in[5];
    const float* bk = (const float*)d_in[6];
    const float* wv = (const float*)d_in[7];
    const float* bv = (const float*)d_in[8];
    const float* gm = (const float*)d_in[9];
    float* out = (float*)d_out;

    const int SM_QK = 64*ASP*4 + 64*68*4;    // 51200
    cudaFuncSetAttribute(proj_qk_kernel, cudaFuncAttributeMaxDynamicSharedMemorySize, SM_QK);

    prep_w_kernel<<<320, 256>>>(wq, wk, wv);
    conv_down_kernel<<<dim3(BB*CC, 16), 256>>>(x, wd);
    resize_a_kernel<<<dim3(4, HW, BB), 256>>>(am);

    proj_qk_kernel<<<dim3(127, BB), 256, SM_QK>>>(bq, bk);
    proj_v_kernel<<<dim3(127, 2, BB), 256>>>(bv);

    energy_e_kernel<false><<<dim3(HW, BB), 256>>>();  // eH (masked)
    energy_e_kernel<true ><<<dim3(HW, BB), 256>>>();  // eW
    energy_a_kernel<false><<<dim3(HW, BB), 256>>>();  // aH (masked)
    energy_a_kernel<true ><<<dim3(HW, BB), 256>>>();  // aW

    softmax3_kernel<<<(BB*SSP + 7)/8, 256>>>();

    outgemm_kernel<false><<<dim3(HW, 2, BB), 256>>>();
    outgemm_kernel<true ><<<dim3(HW, 2, BB), 256>>>();

    final_kernel<<<dim3(8, 32, BB*CC), 256>>>(x, gm, out);
}